// round 6
// baseline (speedup 1.0000x reference)
#include <cuda_runtime.h>

#define NB 16
#define NN 1024
#define ND 1024
#define NU 512

// Scratch (device globals — no allocation allowed).
// g_vh/g_vm are accumulators: zero at module load, and re-zeroed at the end
// of k_outer each call, so every kernel_launch sees them zeroed.
__device__ float g_vh[ND];
__device__ float g_vm[ND];
__device__ float g_c;                 // w_out.(b_h+b_m) + b_out
__device__ float g_sH[NB * NN];       // c folded in by k_rowdots
__device__ float g_sM[NB * NN];

// ---------------------------------------------------------------------------
// Kernel 1: fold the U dimension.
// Blocks 0..255: block owns u-chunk [2*b, 2*b+2), sweeps the full 1024-wide d
// row of both W matrices with float4 loads (warp = 512B contiguous; 4
// independent LDG.128 per thread), REDG-accumulates into g_vh/g_vm
// (256 atomics per address, spread across 2048 addresses -> 184 LTS).
// Block 256: scalar constant c.
// ---------------------------------------------------------------------------
__global__ void k_fold(const float* __restrict__ W_h, const float* __restrict__ W_m,
                       const float* __restrict__ w_out, const float* __restrict__ b_h,
                       const float* __restrict__ b_m, const float* __restrict__ b_out) {
    const int tid = threadIdx.x;

    if (blockIdx.x < 256) {
        const int u0 = blockIdx.x * 2;
        const float4* Wh4 = reinterpret_cast<const float4*>(W_h) + (size_t)u0 * (ND / 4) + tid;
        const float4* Wm4 = reinterpret_cast<const float4*>(W_m) + (size_t)u0 * (ND / 4) + tid;

        const float w0 = __ldg(&w_out[u0]);
        const float w1 = __ldg(&w_out[u0 + 1]);
        const float4 h0 = __ldg(Wh4);
        const float4 h1 = __ldg(Wh4 + (ND / 4));
        const float4 m0 = __ldg(Wm4);
        const float4 m1 = __ldg(Wm4 + (ND / 4));

        float4 ah, am;
        ah.x = fmaf(w1, h1.x, w0 * h0.x); ah.y = fmaf(w1, h1.y, w0 * h0.y);
        ah.z = fmaf(w1, h1.z, w0 * h0.z); ah.w = fmaf(w1, h1.w, w0 * h0.w);
        am.x = fmaf(w1, m1.x, w0 * m0.x); am.y = fmaf(w1, m1.y, w0 * m0.y);
        am.z = fmaf(w1, m1.z, w0 * m0.z); am.w = fmaf(w1, m1.w, w0 * m0.w);

        const int d = tid * 4;
        atomicAdd(&g_vh[d + 0], ah.x); atomicAdd(&g_vh[d + 1], ah.y);
        atomicAdd(&g_vh[d + 2], ah.z); atomicAdd(&g_vh[d + 3], ah.w);
        atomicAdd(&g_vm[d + 0], am.x); atomicAdd(&g_vm[d + 1], am.y);
        atomicAdd(&g_vm[d + 2], am.z); atomicAdd(&g_vm[d + 3], am.w);
    } else {
        __shared__ float red[256];
        float acc = 0.f;
        for (int u = tid; u < NU; u += 256)
            acc = fmaf(w_out[u], b_h[u] + b_m[u], acc);
        red[tid] = acc;
        __syncthreads();
        for (int s = 128; s > 0; s >>= 1) {
            if (tid < s) red[tid] += red[tid + s];
            __syncthreads();
        }
        if (tid == 0) g_c = red[0] + b_out[0];
    }
}

// ---------------------------------------------------------------------------
// Kernel 2: per-token dual dot products. One warp per token row (1024 floats),
// streaming float4 loads (x read exactly once: 64 MiB). c folded into sH.
// ---------------------------------------------------------------------------
__global__ void k_rowdots(const float* __restrict__ x) {
    __shared__ float4 svh[ND / 4];
    __shared__ float4 svm[ND / 4];
    const int tid = threadIdx.x;            // 256 threads = 8 warps
    svh[tid] = reinterpret_cast<const float4*>(g_vh)[tid];
    svm[tid] = reinterpret_cast<const float4*>(g_vm)[tid];
    __syncthreads();

    const int warp = tid >> 5, lane = tid & 31;
    const int row = blockIdx.x * 8 + warp;  // 0 .. NB*NN-1
    const float4* x4 = reinterpret_cast<const float4*>(x) + (size_t)row * (ND / 4);

    float ah = 0.f, am = 0.f;
    #pragma unroll
    for (int k = 0; k < 8; ++k) {
        const int idx = k * 32 + lane;
        const float4 xv = __ldcs(&x4[idx]);
        const float4 vh = svh[idx];
        const float4 vm = svm[idx];
        ah = fmaf(xv.x, vh.x, ah); ah = fmaf(xv.y, vh.y, ah);
        ah = fmaf(xv.z, vh.z, ah); ah = fmaf(xv.w, vh.w, ah);
        am = fmaf(xv.x, vm.x, am); am = fmaf(xv.y, vm.y, am);
        am = fmaf(xv.z, vm.z, am); am = fmaf(xv.w, vm.w, am);
    }
    #pragma unroll
    for (int off = 16; off; off >>= 1) {
        ah += __shfl_xor_sync(0xffffffffu, ah, off);
        am += __shfl_xor_sync(0xffffffffu, am, off);
    }
    if (lane == 0) {
        g_sH[row] = ah + g_c;
        g_sM[row] = am;
    }
}

// ---------------------------------------------------------------------------
// Kernel 3: outer broadcast-add. scores[b,i,j] = sH[b,i] + sM[b,j].
// Grid-stride, 4 float4 per thread, fully coalesced. Tail: re-zero the fold
// accumulators so the next kernel_launch call sees zeros.
// ---------------------------------------------------------------------------
__global__ void k_outer(float* __restrict__ out) {
    const unsigned stride = 2048u * 512u;                 // 1,048,576 float4
    unsigned idx = blockIdx.x * 512u + threadIdx.x;
    const unsigned t0 = idx;

    #pragma unroll
    for (int t = 0; t < 4; ++t, idx += stride) {
        const unsigned j4 = idx & 255u;    // j/4, N/4 = 256
        const unsigned bi = idx >> 8;      // b*N + i
        const unsigned b  = bi >> 10;      // /N

        const float s = g_sH[bi];
        const float4 m = reinterpret_cast<const float4*>(g_sM)[(b << 8) + j4];
        reinterpret_cast<float4*>(out)[idx] =
            make_float4(s + m.x, s + m.y, s + m.z, s + m.w);
    }

    if (t0 < 2 * ND) {                     // re-zero accumulators for next call
        if (t0 < ND) g_vh[t0] = 0.f;
        else         g_vm[t0 - ND] = 0.f;
    }
}

extern "C" void kernel_launch(void* const* d_in, const int* in_sizes, int n_in,
                              void* d_out, int out_size) {
    const float* x     = (const float*)d_in[0];
    const float* W_h   = (const float*)d_in[1];
    const float* b_h   = (const float*)d_in[2];
    const float* W_m   = (const float*)d_in[3];
    const float* b_m   = (const float*)d_in[4];
    const float* w_out = (const float*)d_in[5];
    const float* b_out = (const float*)d_in[6];
    float* out = (float*)d_out;

    k_fold<<<257, 256>>>(W_h, W_m, w_out, b_h, b_m, b_out);
    k_rowdots<<<(NB * NN) / 8, 256>>>(x);
    k_outer<<<2048, 512>>>(out);
}

// round 7
// speedup vs baseline: 1.2890x; 1.2890x over previous
#include <cuda_runtime.h>

#define NB 16
#define NN 1024
#define ND 1024
#define NU 512

// Scratch (device globals — no allocation allowed).
// g_vh/g_vm are accumulators: zero at module load, and re-zeroed at the end
// of k_outer each call, so every kernel_launch sees them zeroed.
__device__ float g_vh[ND];
__device__ float g_vm[ND];
__device__ float g_c;                 // w_out.(b_h+b_m) + b_out
__device__ float g_sH[NB * NN];       // c folded in by k_rowdots
__device__ float g_sM[NB * NN];

// ---------------------------------------------------------------------------
// Kernel 1: fold the U dimension.
// Blocks 0..1023: each block owns a [32u x 32d] tile of W_h (bid<512) or W_m.
//   thread t: urow = t>>3, d4lane = t&7 -> one float4 = 4 d-columns.
//   1 coalesced LDG.128 per thread, smem tree reduces the 32 u-rows,
//   then 8 threads issue 4 atomicAdds each (16 atomics per address total
//   across the grid -> negligible L2-atom serialization).
// Block 1024: scalar constant c.
// All ~262k loads issue in ~1 wave: fold is latency-bound, not BW-bound.
// ---------------------------------------------------------------------------
__global__ void k_fold(const float* __restrict__ W_h, const float* __restrict__ W_m,
                       const float* __restrict__ w_out, const float* __restrict__ b_h,
                       const float* __restrict__ b_m, const float* __restrict__ b_out) {
    const int tid = threadIdx.x;

    if (blockIdx.x < 1024) {
        const bool is_h = blockIdx.x < 512;
        const int t = is_h ? blockIdx.x : blockIdx.x - 512;
        const int uchunk = t >> 5;           // 0..15  -> u0 = 32*uchunk
        const int dgroup = t & 31;           // 0..31  -> d40 = 8*dgroup
        const int urow = tid >> 3;           // 0..31
        const int d4lane = tid & 7;          // 0..7

        const int u = uchunk * 32 + urow;
        const int d4 = dgroup * 8 + d4lane;  // float4 index, 0..255

        const float w = __ldg(&w_out[u]);
        const float4 v = __ldg(reinterpret_cast<const float4*>(is_h ? W_h : W_m)
                               + (size_t)u * (ND / 4) + d4);

        __shared__ float4 sp[256];
        sp[tid] = make_float4(w * v.x, w * v.y, w * v.z, w * v.w);
        __syncthreads();
        #pragma unroll
        for (int s = 128; s >= 8; s >>= 1) {
            if (tid < s) {
                float4 a = sp[tid], b = sp[tid + s];
                sp[tid] = make_float4(a.x + b.x, a.y + b.y, a.z + b.z, a.w + b.w);
            }
            __syncthreads();
        }
        if (tid < 8) {
            float* dst = is_h ? g_vh : g_vm;
            const float4 r = sp[tid];
            const int d = (dgroup * 8 + tid) * 4;
            atomicAdd(&dst[d + 0], r.x); atomicAdd(&dst[d + 1], r.y);
            atomicAdd(&dst[d + 2], r.z); atomicAdd(&dst[d + 3], r.w);
        }
    } else {
        __shared__ float red[256];
        float acc = 0.f;
        for (int u = tid; u < NU; u += 256)
            acc = fmaf(w_out[u], b_h[u] + b_m[u], acc);
        red[tid] = acc;
        __syncthreads();
        for (int s = 128; s > 0; s >>= 1) {
            if (tid < s) red[tid] += red[tid + s];
            __syncthreads();
        }
        if (tid == 0) g_c = red[0] + b_out[0];
    }
}

// ---------------------------------------------------------------------------
// Kernel 2: per-token dual dot products. One warp per token row (1024 floats),
// streaming float4 loads (x read exactly once: 64 MiB). c folded into sH.
// ---------------------------------------------------------------------------
__global__ void k_rowdots(const float* __restrict__ x) {
    __shared__ float4 svh[ND / 4];
    __shared__ float4 svm[ND / 4];
    const int tid = threadIdx.x;            // 256 threads = 8 warps
    svh[tid] = reinterpret_cast<const float4*>(g_vh)[tid];
    svm[tid] = reinterpret_cast<const float4*>(g_vm)[tid];
    __syncthreads();

    const int warp = tid >> 5, lane = tid & 31;
    const int row = blockIdx.x * 8 + warp;  // 0 .. NB*NN-1
    const float4* x4 = reinterpret_cast<const float4*>(x) + (size_t)row * (ND / 4);

    float ah = 0.f, am = 0.f;
    #pragma unroll
    for (int k = 0; k < 8; ++k) {
        const int idx = k * 32 + lane;
        const float4 xv = __ldcs(&x4[idx]);
        const float4 vh = svh[idx];
        const float4 vm = svm[idx];
        ah = fmaf(xv.x, vh.x, ah); ah = fmaf(xv.y, vh.y, ah);
        ah = fmaf(xv.z, vh.z, ah); ah = fmaf(xv.w, vh.w, ah);
        am = fmaf(xv.x, vm.x, am); am = fmaf(xv.y, vm.y, am);
        am = fmaf(xv.z, vm.z, am); am = fmaf(xv.w, vm.w, am);
    }
    #pragma unroll
    for (int off = 16; off; off >>= 1) {
        ah += __shfl_xor_sync(0xffffffffu, ah, off);
        am += __shfl_xor_sync(0xffffffffu, am, off);
    }
    if (lane == 0) {
        g_sH[row] = ah + g_c;
        g_sM[row] = am;
    }
}

// ---------------------------------------------------------------------------
// Kernel 3: outer broadcast-add. scores[b,i,j] = sH[b,i] + sM[b,j].
// Grid-stride, 4 float4 per thread, fully coalesced. Tail: re-zero the fold
// accumulators so the next kernel_launch call sees zeros.
// ---------------------------------------------------------------------------
__global__ void k_outer(float* __restrict__ out) {
    const unsigned stride = 2048u * 512u;                 // 1,048,576 float4
    unsigned idx = blockIdx.x * 512u + threadIdx.x;
    const unsigned t0 = idx;

    #pragma unroll
    for (int t = 0; t < 4; ++t, idx += stride) {
        const unsigned j4 = idx & 255u;    // j/4, N/4 = 256
        const unsigned bi = idx >> 8;      // b*N + i
        const unsigned b  = bi >> 10;      // /N

        const float s = g_sH[bi];
        const float4 m = reinterpret_cast<const float4*>(g_sM)[(b << 8) + j4];
        reinterpret_cast<float4*>(out)[idx] =
            make_float4(s + m.x, s + m.y, s + m.z, s + m.w);
    }

    if (t0 < 2 * ND) {                     // re-zero accumulators for next call
        if (t0 < ND) g_vh[t0] = 0.f;
        else         g_vm[t0 - ND] = 0.f;
    }
}

extern "C" void kernel_launch(void* const* d_in, const int* in_sizes, int n_in,
                              void* d_out, int out_size) {
    const float* x     = (const float*)d_in[0];
    const float* W_h   = (const float*)d_in[1];
    const float* b_h   = (const float*)d_in[2];
    const float* W_m   = (const float*)d_in[3];
    const float* b_m   = (const float*)d_in[4];
    const float* w_out = (const float*)d_in[5];
    const float* b_out = (const float*)d_in[6];
    float* out = (float*)d_out;

    k_fold<<<1025, 256>>>(W_h, W_m, w_out, b_h, b_m, b_out);
    k_rowdots<<<(NB * NN) / 8, 256>>>(x);
    k_outer<<<2048, 512>>>(out);
}

// round 9
// speedup vs baseline: 1.3493x; 1.0468x over previous
#include <cuda_runtime.h>

#define NB 16
#define NN 1024
#define ND 1024
#define NU 512

// Scratch (device globals — no allocation allowed).
// g_vh/g_vm are accumulators: zero at module load, and re-zeroed at the end
// of k_outer each call, so every kernel_launch sees them zeroed.
__device__ float g_vh[ND];
__device__ float g_vm[ND];
__device__ float g_c;                 // w_out.(b_h+b_m) + b_out
__device__ float g_sH[NB * NN];       // c folded in by k_rowdots
__device__ float g_sM[NB * NN];

// ---------------------------------------------------------------------------
// Kernel 1: fold the U dimension.
// Blocks 0..255: each block owns a [32u x 128d] tile of W_h (bid<128) or W_m.
//   Thread: d4 = dtile*32 + (tid&31), warp row group = tid>>5 (8 groups);
//   register-accumulates 4 u-rows (stride 8) -> 4 independent coalesced
//   LDG.128 (warp = 512B contiguous). 3-round smem tree collapses the 8
//   warp partials; warp 0 issues 4 atomicAdds/lane (16 atomics per address
//   grid-wide -> contention-free).
// Block 256: scalar constant c.
// ---------------------------------------------------------------------------
__global__ void k_fold(const float* __restrict__ W_h, const float* __restrict__ W_m,
                       const float* __restrict__ w_out, const float* __restrict__ b_h,
                       const float* __restrict__ b_m, const float* __restrict__ b_out) {
    const int tid = threadIdx.x;

    if (blockIdx.x < 256) {
        const bool is_h = blockIdx.x < 128;
        const int t = is_h ? blockIdx.x : blockIdx.x - 128;
        const int utile = t >> 3;            // 0..15 -> u0 = 32*utile
        const int dtile = t & 7;             // 0..7  -> d4 base = 32*dtile
        const int wgrp  = tid >> 5;          // 0..7
        const int d4    = dtile * 32 + (tid & 31);

        const float4* W4 = reinterpret_cast<const float4*>(is_h ? W_h : W_m);
        const int u_base = utile * 32 + wgrp;

        float4 acc = make_float4(0.f, 0.f, 0.f, 0.f);
        #pragma unroll
        for (int k = 0; k < 4; ++k) {
            const int u = u_base + k * 8;
            const float w = __ldg(&w_out[u]);
            const float4 v = __ldg(W4 + (size_t)u * (ND / 4) + d4);
            acc.x = fmaf(w, v.x, acc.x); acc.y = fmaf(w, v.y, acc.y);
            acc.z = fmaf(w, v.z, acc.z); acc.w = fmaf(w, v.w, acc.w);
        }

        __shared__ float4 sp[256];
        sp[tid] = acc;
        __syncthreads();
        #pragma unroll
        for (int s = 128; s >= 32; s >>= 1) {
            if (tid < s) {
                float4 a = sp[tid], b = sp[tid + s];
                sp[tid] = make_float4(a.x + b.x, a.y + b.y, a.z + b.z, a.w + b.w);
            }
            __syncthreads();
        }
        if (tid < 32) {
            float* dst = is_h ? g_vh : g_vm;
            const float4 r = sp[tid];
            const int d = (dtile * 32 + tid) * 4;
            atomicAdd(&dst[d + 0], r.x); atomicAdd(&dst[d + 1], r.y);
            atomicAdd(&dst[d + 2], r.z); atomicAdd(&dst[d + 3], r.w);
        }
    } else {
        __shared__ float red[256];
        float acc = 0.f;
        for (int u = tid; u < NU; u += 256)
            acc = fmaf(w_out[u], b_h[u] + b_m[u], acc);
        red[tid] = acc;
        __syncthreads();
        for (int s = 128; s > 0; s >>= 1) {
            if (tid < s) red[tid] += red[tid + s];
            __syncthreads();
        }
        if (tid == 0) g_c = red[0] + b_out[0];
    }
}

// ---------------------------------------------------------------------------
// Kernel 2: per-token dual dot products. One warp per token row (1024 floats),
// streaming float4 loads (x read exactly once: 64 MiB). c folded into sH.
// ---------------------------------------------------------------------------
__global__ void k_rowdots(const float* __restrict__ x) {
    __shared__ float4 svh[ND / 4];
    __shared__ float4 svm[ND / 4];
    const int tid = threadIdx.x;            // 256 threads = 8 warps
    svh[tid] = reinterpret_cast<const float4*>(g_vh)[tid];
    svm[tid] = reinterpret_cast<const float4*>(g_vm)[tid];
    __syncthreads();

    const int warp = tid >> 5, lane = tid & 31;
    const int row = blockIdx.x * 8 + warp;  // 0 .. NB*NN-1
    const float4* x4 = reinterpret_cast<const float4*>(x) + (size_t)row * (ND / 4);

    float ah = 0.f, am = 0.f;
    #pragma unroll
    for (int k = 0; k < 8; ++k) {
        const int idx = k * 32 + lane;
        const float4 xv = __ldcs(&x4[idx]);
        const float4 vh = svh[idx];
        const float4 vm = svm[idx];
        ah = fmaf(xv.x, vh.x, ah); ah = fmaf(xv.y, vh.y, ah);
        ah = fmaf(xv.z, vh.z, ah); ah = fmaf(xv.w, vh.w, ah);
        am = fmaf(xv.x, vm.x, am); am = fmaf(xv.y, vm.y, am);
        am = fmaf(xv.z, vm.z, am); am = fmaf(xv.w, vm.w, am);
    }
    #pragma unroll
    for (int off = 16; off; off >>= 1) {
        ah += __shfl_xor_sync(0xffffffffu, ah, off);
        am += __shfl_xor_sync(0xffffffffu, am, off);
    }
    if (lane == 0) {
        g_sH[row] = ah + g_c;
        g_sM[row] = am;
    }
}

// ---------------------------------------------------------------------------
// Kernel 3: outer broadcast-add. scores[b,i,j] = sH[b,i] + sM[b,j].
// Grid-stride, 4 float4 per thread, fully coalesced. Tail: re-zero the fold
// accumulators so the next kernel_launch call sees zeros.
// ---------------------------------------------------------------------------
__global__ void k_outer(float* __restrict__ out) {
    const unsigned stride = 2048u * 512u;                 // 1,048,576 float4
    unsigned idx = blockIdx.x * 512u + threadIdx.x;
    const unsigned t0 = idx;

    #pragma unroll
    for (int t = 0; t < 4; ++t, idx += stride) {
        const unsigned j4 = idx & 255u;    // j/4, N/4 = 256
        const unsigned bi = idx >> 8;      // b*N + i
        const unsigned b  = bi >> 10;      // /N

        const float s = g_sH[bi];
        const float4 m = reinterpret_cast<const float4*>(g_sM)[(b << 8) + j4];
        reinterpret_cast<float4*>(out)[idx] =
            make_float4(s + m.x, s + m.y, s + m.z, s + m.w);
    }

    if (t0 < 2 * ND) {                     // re-zero accumulators for next call
        if (t0 < ND) g_vh[t0] = 0.f;
        else         g_vm[t0 - ND] = 0.f;
    }
}

extern "C" void kernel_launch(void* const* d_in, const int* in_sizes, int n_in,
                              void* d_out, int out_size) {
    const float* x     = (const float*)d_in[0];
    const float* W_h   = (const float*)d_in[1];
    const float* b_h   = (const float*)d_in[2];
    const float* W_m   = (const float*)d_in[3];
    const float* b_m   = (const float*)d_in[4];
    const float* w_out = (const float*)d_in[5];
    const float* b_out = (const float*)d_in[6];
    float* out = (float*)d_out;

    k_fold<<<257, 256>>>(W_h, W_m, w_out, b_h, b_m, b_out);
    k_rowdots<<<(NB * NN) / 8, 256>>>(x);
    k_outer<<<2048, 512>>>(out);
}